// round 2
// baseline (speedup 1.0000x reference)
#include <cuda_runtime.h>
#include <cstdint>

// Per-block partial counters, written unconditionally every launch (no zeroing needed).
// Layout: g_partials[k * MAX_BLOCKS + blockIdx] for coalesced final reduction.
#define MAX_BLOCKS 1280
__device__ unsigned int g_partials[9 * MAX_BLOCKS];

struct Cnts {
    unsigned int c[9]; // 0..2: vol1==l, 3..5: vol2==l, 6..8: both
};

__device__ __forceinline__ void accum_lane(float x, float y,
    unsigned int& c0, unsigned int& c1, unsigned int& c2,
    unsigned int& d0, unsigned int& d1, unsigned int& d2,
    unsigned int& i0, unsigned int& i1, unsigned int& i2)
{
    bool m1 = (x == 1.0f), m2 = (x == 2.0f), m3 = (x == 3.0f);
    bool n1 = (y == 1.0f), n2 = (y == 2.0f), n3 = (y == 3.0f);
    c0 += m1; c1 += m2; c2 += m3;
    d0 += n1; d1 += n2; d2 += n3;
    i0 += (m1 & n1); i1 += (m2 & n2); i2 += (m3 & n3);
}

__global__ void __launch_bounds__(256) dice_count_kernel(
    const float4* __restrict__ a, const float4* __restrict__ b, int n_vec)
{
    unsigned int c0 = 0, c1 = 0, c2 = 0;
    unsigned int d0 = 0, d1 = 0, d2 = 0;
    unsigned int i0 = 0, i1 = 0, i2 = 0;

    const int stride = gridDim.x * blockDim.x;
    int idx = blockIdx.x * blockDim.x + threadIdx.x;

    #pragma unroll 4
    for (; idx < n_vec; idx += stride) {
        float4 va = __ldcs(&a[idx]);
        float4 vb = __ldcs(&b[idx]);
        accum_lane(va.x, vb.x, c0, c1, c2, d0, d1, d2, i0, i1, i2);
        accum_lane(va.y, vb.y, c0, c1, c2, d0, d1, d2, i0, i1, i2);
        accum_lane(va.z, vb.z, c0, c1, c2, d0, d1, d2, i0, i1, i2);
        accum_lane(va.w, vb.w, c0, c1, c2, d0, d1, d2, i0, i1, i2);
    }

    unsigned int v[9] = {c0, c1, c2, d0, d1, d2, i0, i1, i2};
    #pragma unroll
    for (int k = 0; k < 9; ++k) {
        #pragma unroll
        for (int off = 16; off > 0; off >>= 1)
            v[k] += __shfl_down_sync(0xFFFFFFFFu, v[k], off);
    }

    __shared__ unsigned int s[9];
    if (threadIdx.x < 9) s[threadIdx.x] = 0u;
    __syncthreads();
    if ((threadIdx.x & 31) == 0) {
        #pragma unroll
        for (int k = 0; k < 9; ++k) atomicAdd(&s[k], v[k]);
    }
    __syncthreads();
    // Unconditional per-block write: deterministic, no stale state across launches.
    if (threadIdx.x < 9)
        g_partials[threadIdx.x * MAX_BLOCKS + blockIdx.x] = s[threadIdx.x];
}

__global__ void __launch_bounds__(256) dice_final_kernel(float* __restrict__ out, int n_blocks)
{
    // Reduce 9 x n_blocks partials with one 256-thread block.
    __shared__ unsigned int totals[9];

    #pragma unroll
    for (int k = 0; k < 9; ++k) {
        unsigned int local = 0;
        for (int i = threadIdx.x; i < n_blocks; i += 256)
            local += g_partials[k * MAX_BLOCKS + i];
        #pragma unroll
        for (int off = 16; off > 0; off >>= 1)
            local += __shfl_down_sync(0xFFFFFFFFu, local, off);
        __shared__ unsigned int warp_sums[8];
        if ((threadIdx.x & 31) == 0) warp_sums[threadIdx.x >> 5] = local;
        __syncthreads();
        if (threadIdx.x == 0) {
            unsigned int t = 0;
            #pragma unroll
            for (int w = 0; w < 8; ++w) t += warp_sums[w];
            totals[k] = t;
        }
        __syncthreads();
    }

    if (threadIdx.x == 0) {
        const float eps = 1.1920928955078125e-07f;  // np.finfo(float32).eps
        float sum = 0.0f;
        #pragma unroll
        for (int l = 0; l < 3; ++l) {
            float inter = (float)totals[6 + l];
            float bot   = (float)totals[l] + (float)totals[3 + l];
            sum += (2.0f * inter) / (bot + eps);
        }
        out[0] = 1.0f - sum * (1.0f / 3.0f);
    }
}

extern "C" void kernel_launch(void* const* d_in, const int* in_sizes, int n_in,
                              void* d_out, int out_size)
{
    const float4* a = (const float4*)d_in[0];
    const float4* b = (const float4*)d_in[1];
    float* out = (float*)d_out;

    int n = in_sizes[0];        // 512^3, divisible by 4
    int n_vec = n >> 2;

    const int threads = 256;
    const int blocks  = 152 * 8;   // 1216 <= MAX_BLOCKS
    dice_count_kernel<<<blocks, threads>>>(a, b, n_vec);
    dice_final_kernel<<<1, threads>>>(out, blocks);
}

// round 3
// speedup vs baseline: 1.0477x; 1.0477x over previous
#include <cuda_runtime.h>
#include <cstdint>

// Accumulators + completion ticket. Zero-initialized at module load; the last
// block of every launch resets them to zero, so every launch (and every graph
// replay) starts from a clean state. Integer atomics -> order-independent ->
// deterministic.
__device__ unsigned int g_counts[9];
__device__ unsigned int g_ticket;

__device__ __forceinline__ void accum_lane(float x, float y,
    unsigned int& c0, unsigned int& c1, unsigned int& c2,
    unsigned int& d0, unsigned int& d1, unsigned int& d2,
    unsigned int& i0, unsigned int& i1, unsigned int& i2)
{
    bool m1 = (x == 1.0f), m2 = (x == 2.0f), m3 = (x == 3.0f);
    bool n1 = (y == 1.0f), n2 = (y == 2.0f), n3 = (y == 3.0f);
    c0 += m1; c1 += m2; c2 += m3;
    d0 += n1; d1 += n2; d2 += n3;
    i0 += (m1 & n1); i1 += (m2 & n2); i2 += (m3 & n3);
}

__global__ void __launch_bounds__(256) dice_fused_kernel(
    const float4* __restrict__ a, const float4* __restrict__ b,
    int n_vec, float* __restrict__ out)
{
    unsigned int c0 = 0, c1 = 0, c2 = 0;
    unsigned int d0 = 0, d1 = 0, d2 = 0;
    unsigned int i0 = 0, i1 = 0, i2 = 0;

    const int stride = gridDim.x * blockDim.x;
    int idx = blockIdx.x * blockDim.x + threadIdx.x;

    #pragma unroll 4
    for (; idx < n_vec; idx += stride) {
        float4 va = __ldcs(&a[idx]);
        float4 vb = __ldcs(&b[idx]);
        accum_lane(va.x, vb.x, c0, c1, c2, d0, d1, d2, i0, i1, i2);
        accum_lane(va.y, vb.y, c0, c1, c2, d0, d1, d2, i0, i1, i2);
        accum_lane(va.z, vb.z, c0, c1, c2, d0, d1, d2, i0, i1, i2);
        accum_lane(va.w, vb.w, c0, c1, c2, d0, d1, d2, i0, i1, i2);
    }

    // warp reduce 9 counters
    unsigned int v[9] = {c0, c1, c2, d0, d1, d2, i0, i1, i2};
    #pragma unroll
    for (int k = 0; k < 9; ++k) {
        #pragma unroll
        for (int off = 16; off > 0; off >>= 1)
            v[k] += __shfl_down_sync(0xFFFFFFFFu, v[k], off);
    }

    // block reduce via shared atomics
    __shared__ unsigned int s[9];
    __shared__ bool is_last;
    if (threadIdx.x < 9) s[threadIdx.x] = 0u;
    __syncthreads();
    if ((threadIdx.x & 31) == 0) {
        #pragma unroll
        for (int k = 0; k < 9; ++k) atomicAdd(&s[k], v[k]);
    }
    __syncthreads();

    // global accumulate, then take a ticket; last block finalizes.
    if (threadIdx.x < 9) atomicAdd(&g_counts[threadIdx.x], s[threadIdx.x]);
    __threadfence();
    if (threadIdx.x == 0) {
        unsigned int t = atomicAdd(&g_ticket, 1u);
        is_last = (t == gridDim.x - 1u);
    }
    __syncthreads();

    if (is_last && threadIdx.x == 0) {
        // All blocks' atomics are globally visible (each fenced before its
        // ticket increment, and we observed the final ticket).
        unsigned int tot[9];
        #pragma unroll
        for (int k = 0; k < 9; ++k)
            tot[k] = atomicAdd(&g_counts[k], 0u);  // atomic read-after-fence

        const float eps = 1.1920928955078125e-07f;  // np.finfo(float32).eps
        float sum = 0.0f;
        #pragma unroll
        for (int l = 0; l < 3; ++l) {
            float inter = (float)tot[6 + l];
            float bot   = (float)tot[l] + (float)tot[3 + l];
            sum += (2.0f * inter) / (bot + eps);
        }
        out[0] = 1.0f - sum * (1.0f / 3.0f);

        // reset state for the next launch / graph replay
        #pragma unroll
        for (int k = 0; k < 9; ++k) g_counts[k] = 0u;
        __threadfence();
        g_ticket = 0u;
    }
}

extern "C" void kernel_launch(void* const* d_in, const int* in_sizes, int n_in,
                              void* d_out, int out_size)
{
    const float4* a = (const float4*)d_in[0];
    const float4* b = (const float4*)d_in[1];
    float* out = (float*)d_out;

    int n = in_sizes[0];        // 512^3, divisible by 4
    int n_vec = n >> 2;

    const int threads = 256;
    const int blocks  = 152 * 8;
    dice_fused_kernel<<<blocks, threads>>>(a, b, n_vec, out);
}